// round 16
// baseline (speedup 1.0000x reference)
#include <cuda_runtime.h>
#include <cuda_bf16.h>
#include <cstdint>

// out[b,g,k] = sum_d (h[b,g,d]/||h||) * (w[g,d,k]/||w_col||)
// B=512, G=100, D=768, K=100.
// bf16 two-term split, 3-product HMMA, fp32 acc, double-buffered smem.
// Both norms commuted into the GEMM epilogue.
// W scratch in native [g][d][k] orientation; prep reads w EXACTLY ONCE:
// streaming convert + in-block deterministic sumsq partials.
// (R16 fix: slot-10 partial smem zero-filled; reduce all slots.)

#define B_ 512
#define G_ 100
#define D_ 768
#define K_ 100
#define KP 128
#define BKC 32              // k-chunk (d dimension)
#define NCHUNK (D_ / BKC)   // 24
#define LDB 80              // A smem row stride bytes (32 bf16 + pad)
#define LDBB 272            // B smem row stride bytes (128 bf16 + 16B pad)

#define AH_OFF 0            // 128 rows * 80  = 10240
#define AL_OFF 10240
#define BH_OFF 20480        // 32 rows * 272  = 8704
#define BL_OFF 29184
#define STAGE_BYTES 37888

#define NBLK_PER_G 75       // convert blocks per group (exact: 19200/256)
#define NPREP (G_ * NBLK_PER_G)   // 7500

// ---------------- device scratch ----------------
__device__ float g_wblk[NPREP * 128];       // per-block sumsq partials [bz][k]
__device__ float g_inv_w2[G_ * 128];        // invw table [g][k] (0 for k>=100)
__device__ __nv_bfloat16 g_wt_hi[(size_t)G_ * D_ * KP];   // [g][d][k], .bss zeros
__device__ __nv_bfloat16 g_wt_lo[(size_t)G_ * D_ * KP];

// ---------------- helpers ----------------
__device__ __forceinline__ uint32_t smem_u32(const void* p) {
    uint32_t a;
    asm("{ .reg .u64 t; cvta.to.shared.u64 t, %1; cvt.u32.u64 %0, t; }"
        : "=r"(a) : "l"(p));
    return a;
}

#define MMA_BF16(d, a, b0, b1)                                              \
    asm volatile(                                                           \
        "mma.sync.aligned.m16n8k16.row.col.f32.bf16.bf16.f32 "              \
        "{%0,%1,%2,%3}, {%4,%5,%6,%7}, {%8,%9}, {%0,%1,%2,%3};"             \
        : "+f"(d[0]), "+f"(d[1]), "+f"(d[2]), "+f"(d[3])                    \
        : "r"(a[0]), "r"(a[1]), "r"(a[2]), "r"(a[3]), "r"(b0), "r"(b1))

#define LDSM4(r, addr)                                                      \
    asm volatile("ldmatrix.sync.aligned.m8n8.x4.shared.b16 "                \
                 "{%0,%1,%2,%3}, [%4];"                                     \
                 : "=r"((r)[0]), "=r"((r)[1]), "=r"((r)[2]), "=r"((r)[3])   \
                 : "r"(addr))

#define LDSM4T(r, addr)                                                     \
    asm volatile("ldmatrix.sync.aligned.m8n8.x4.trans.shared.b16 "          \
                 "{%0,%1,%2,%3}, [%4];"                                     \
                 : "=r"((r)[0]), "=r"((r)[1]), "=r"((r)[2]), "=r"((r)[3])   \
                 : "r"(addr))

#define CP16(dst, src)                                                      \
    asm volatile("cp.async.cg.shared.global [%0], [%1], 16;"                \
                 :: "r"(dst), "l"(src) : "memory")
#define CP_COMMIT() asm volatile("cp.async.commit_group;" ::: "memory")
#define CP_WAIT0()  asm volatile("cp.async.wait_group 0;" ::: "memory")

// ---------------------------------------------------------------------------
// prep_w: 7500 blocks x 256 threads. Each block = 256 k-quads of ONE group
// (75 blocks per g exactly). Streaming convert w -> unnormalized bf16 hi/lo
// (native [g][d][k]), plus deterministic in-block sumsq partial per k-quad.
// slot = tid/25 (0..10); j = global quad % 25. Slots 0..9 are fully written;
// slot 10 gets only 6 bz-dependent j's -> pre-zero it and reduce all slots.
// ---------------------------------------------------------------------------
__global__ void prep_w_kernel(const float* __restrict__ w) {
    __shared__ float4 part[11][25];            // [slot][j]
    const int bz  = blockIdx.x;
    const int tid = threadIdx.x;
    const int t   = bz * 256 + tid;            // quad index
    const int row = t / 25;                    // g*D + d
    const int j   = t % 25;                    // k = 4j..4j+3

    // zero-fill the partially-written slot 10
    if (tid < 25) part[10][tid] = make_float4(0.f, 0.f, 0.f, 0.f);
    __syncthreads();

    float4 v = *reinterpret_cast<const float4*>(w + (size_t)row * K_ + 4 * j);

    // convert to hi/lo bf16
    __nv_bfloat162 h0 = __float22bfloat162_rn(make_float2(v.x, v.y));
    __nv_bfloat162 h1 = __float22bfloat162_rn(make_float2(v.z, v.w));
    float2 f0 = __bfloat1622float2(h0), f1 = __bfloat1622float2(h1);
    __nv_bfloat162 l0 = __float22bfloat162_rn(make_float2(v.x - f0.x, v.y - f0.y));
    __nv_bfloat162 l1 = __float22bfloat162_rn(make_float2(v.z - f1.x, v.w - f1.y));
    uint2 uh, ul;
    uh.x = *reinterpret_cast<uint32_t*>(&h0);
    uh.y = *reinterpret_cast<uint32_t*>(&h1);
    ul.x = *reinterpret_cast<uint32_t*>(&l0);
    ul.y = *reinterpret_cast<uint32_t*>(&l1);
    *reinterpret_cast<uint2*>(g_wt_hi + (size_t)row * KP + 4 * j) = uh;
    *reinterpret_cast<uint2*>(g_wt_lo + (size_t)row * KP + 4 * j) = ul;

    // deterministic per-k-quad sumsq partial
    part[tid / 25][j] = make_float4(v.x * v.x, v.y * v.y, v.z * v.z, v.w * v.w);
    __syncthreads();
    if (tid < 25) {
        float4 s = make_float4(0.f, 0.f, 0.f, 0.f);
#pragma unroll
        for (int slot = 0; slot < 11; slot++) {
            float4 p = part[slot][tid];
            s.x += p.x; s.y += p.y; s.z += p.z; s.w += p.w;
        }
        *reinterpret_cast<float4*>(g_wblk + (size_t)bz * 128 + 4 * tid) = s;
    }
}

// ---------------------------------------------------------------------------
// combine: invw table from 75 per-block partials. 100 blocks x 128 threads.
// ---------------------------------------------------------------------------
__global__ void combine_w_kernel() {
    const int g = blockIdx.x;
    const int k = threadIdx.x;
    float s = 0.f;
    const float* base = g_wblk + (size_t)g * NBLK_PER_G * 128 + k;
#pragma unroll 5
    for (int b = 0; b < NBLK_PER_G; b++)
        s += base[(size_t)b * 128];
    g_inv_w2[g * 128 + k] = (k < K_) ? 1.0f / fmaxf(sqrtf(s), 1e-12f) : 0.f;
}

// ---------------------------------------------------------------------------
// HMMA GEMM. CTA = (g, 128 rows), 8 warps: mw = warp&1 (64 rows),
// nw = warp>>1 (32 cols). Warp tile 64x32, 3 bf16 products, fp32 acc.
// A raw-split with sumsq; B tiles k-major [32d][128k] via ldmatrix.trans;
// invh and invw applied in epilogue.
// ---------------------------------------------------------------------------
__global__ __launch_bounds__(256, 2)
void gemm_hmma_kernel(const float* __restrict__ h, float* __restrict__ out) {
    extern __shared__ char smem[];
    const uint32_t sb = smem_u32(smem);
    const int tid  = threadIdx.x;
    const int lane = tid & 31;
    const int warp = tid >> 5;
    const int mw = warp & 1;
    const int nw = warp >> 1;
    const int g  = blockIdx.y;
    const int m0 = blockIdx.x * 128;

    // ---- A global mapping: 2 threads per row, 16 elems each ----
    const int arow = tid >> 1;
    const int half = tid & 1;
    const float* gA = h + ((size_t)(m0 + arow) * G_ + g) * D_ + half * 16;
    const uint32_t srow = arow * LDB + half * 32;

    // ---- B global mapping: chunk is 8KB contiguous [32 d][128 k] ----
    const char* gB_h = reinterpret_cast<const char*>(g_wt_hi + (size_t)g * D_ * KP);
    const char* gB_l = reinterpret_cast<const char*>(g_wt_lo + (size_t)g * D_ * KP);
    const int bid0 = tid, bid1 = tid + 256;
    const uint32_t bsrc0 = (bid0 >> 4) * 256 + (bid0 & 15) * 16;
    const uint32_t bdst0 = (bid0 >> 4) * LDBB + (bid0 & 15) * 16;
    const uint32_t bsrc1 = (bid1 >> 4) * 256 + (bid1 & 15) * 16;
    const uint32_t bdst1 = (bid1 >> 4) * LDBB + (bid1 & 15) * 16;

    // ldmatrix base addresses (stage-relative)
    const uint32_t a_lm = (mw * 64 + (lane & 15)) * LDB + (lane >> 4) * 16;
    const uint32_t b_lm = (((lane >> 3) & 1) * 8 + (lane & 7)) * LDBB
                        + (lane >> 4) * 16 + nw * 64;

    float acc[4][4][4];   // [mt][nf][reg]
#pragma unroll
    for (int mt = 0; mt < 4; mt++)
#pragma unroll
        for (int nf = 0; nf < 4; nf++)
#pragma unroll
            for (int r = 0; r < 4; r++) acc[mt][nf][r] = 0.f;

    float sumsq = 0.f;

    // ---- A convert+store: 16 fp32 -> hi/lo bf16, accumulate sumsq ----
    auto store_A = [&](const float4* av, uint32_t stage) {
        uint32_t uh[8], ul[8];
#pragma unroll
        for (int i = 0; i < 4; i++) {
            float x0 = av[i].x, x1 = av[i].y, x2 = av[i].z, x3 = av[i].w;
            sumsq = fmaf(x0, x0, sumsq);
            sumsq = fmaf(x1, x1, sumsq);
            sumsq = fmaf(x2, x2, sumsq);
            sumsq = fmaf(x3, x3, sumsq);
            __nv_bfloat162 h0 = __float22bfloat162_rn(make_float2(x0, x1));
            __nv_bfloat162 h1 = __float22bfloat162_rn(make_float2(x2, x3));
            float2 f0 = __bfloat1622float2(h0), f1 = __bfloat1622float2(h1);
            __nv_bfloat162 l0 = __float22bfloat162_rn(make_float2(x0 - f0.x, x1 - f0.y));
            __nv_bfloat162 l1 = __float22bfloat162_rn(make_float2(x2 - f1.x, x3 - f1.y));
            uh[i * 2]     = *reinterpret_cast<uint32_t*>(&h0);
            uh[i * 2 + 1] = *reinterpret_cast<uint32_t*>(&h1);
            ul[i * 2]     = *reinterpret_cast<uint32_t*>(&l0);
            ul[i * 2 + 1] = *reinterpret_cast<uint32_t*>(&l1);
        }
        asm volatile("st.shared.v4.b32 [%0], {%1,%2,%3,%4};"
            :: "r"(stage + AH_OFF + srow), "r"(uh[0]), "r"(uh[1]), "r"(uh[2]), "r"(uh[3]) : "memory");
        asm volatile("st.shared.v4.b32 [%0], {%1,%2,%3,%4};"
            :: "r"(stage + AH_OFF + srow + 16), "r"(uh[4]), "r"(uh[5]), "r"(uh[6]), "r"(uh[7]) : "memory");
        asm volatile("st.shared.v4.b32 [%0], {%1,%2,%3,%4};"
            :: "r"(stage + AL_OFF + srow), "r"(ul[0]), "r"(ul[1]), "r"(ul[2]), "r"(ul[3]) : "memory");
        asm volatile("st.shared.v4.b32 [%0], {%1,%2,%3,%4};"
            :: "r"(stage + AL_OFF + srow + 16), "r"(ul[4]), "r"(ul[5]), "r"(ul[6]), "r"(ul[7]) : "memory");
    };

    auto cp_B = [&](int c, uint32_t stage) {
        const char* sh = gB_h + (size_t)c * 8192;
        const char* sl = gB_l + (size_t)c * 8192;
        CP16(stage + BH_OFF + bdst0, sh + bsrc0);
        CP16(stage + BH_OFF + bdst1, sh + bsrc1);
        CP16(stage + BL_OFF + bdst0, sl + bsrc0);
        CP16(stage + BL_OFF + bdst1, sl + bsrc1);
    };

    // ---- prologue: fill stage 0 ----
    {
        float4 av[4];
#pragma unroll
        for (int i = 0; i < 4; i++)
            av[i] = *reinterpret_cast<const float4*>(gA + i * 4);
        cp_B(0, sb);
        CP_COMMIT();
        store_A(av, sb);
        CP_WAIT0();
    }
    __syncthreads();

    for (int c = 0; c < NCHUNK; c++) {
        const uint32_t stage  = sb + (uint32_t)(c & 1) * STAGE_BYTES;
        const uint32_t nstage = sb + (uint32_t)((c + 1) & 1) * STAGE_BYTES;

        float4 av[4];
        if (c + 1 < NCHUNK) {
#pragma unroll
            for (int i = 0; i < 4; i++)
                av[i] = *reinterpret_cast<const float4*>(gA + (c + 1) * BKC + i * 4);
            cp_B(c + 1, nstage);
            CP_COMMIT();
        }

        // ---- compute current chunk: 2 k16-steps ----
#pragma unroll
        for (int ks = 0; ks < 2; ks++) {
            const uint32_t koA = ks * 32;           // A: 16 bf16 = 32 bytes
            const uint32_t koB = ks * 16 * LDBB;    // B: 16 k-rows
            uint32_t bh[2][4], bl[2][4];
#pragma unroll
            for (int nhalf = 0; nhalf < 2; nhalf++) {
                LDSM4T(bh[nhalf], stage + BH_OFF + koB + b_lm + nhalf * 32);
                LDSM4T(bl[nhalf], stage + BL_OFF + koB + b_lm + nhalf * 32);
            }
#pragma unroll
            for (int mt = 0; mt < 4; mt++) {
                uint32_t ah[4], al[4];
                LDSM4(ah, stage + AH_OFF + a_lm + mt * (16 * LDB) + koA);
                LDSM4(al, stage + AL_OFF + a_lm + mt * (16 * LDB) + koA);
#pragma unroll
                for (int nf = 0; nf < 4; nf++)
                    MMA_BF16(acc[mt][nf], ah,
                             bh[nf >> 1][(nf & 1) * 2], bh[nf >> 1][(nf & 1) * 2 + 1]);
#pragma unroll
                for (int nf = 0; nf < 4; nf++)
                    MMA_BF16(acc[mt][nf], ah,
                             bl[nf >> 1][(nf & 1) * 2], bl[nf >> 1][(nf & 1) * 2 + 1]);
#pragma unroll
                for (int nf = 0; nf < 4; nf++)
                    MMA_BF16(acc[mt][nf], al,
                             bh[nf >> 1][(nf & 1) * 2], bh[nf >> 1][(nf & 1) * 2 + 1]);
            }
        }

        if (c + 1 < NCHUNK) {
            store_A(av, nstage);
            CP_WAIT0();
        }
        __syncthreads();
    }

    // ---- row-norm exchange ----
    sumsq += __shfl_xor_sync(0xffffffffu, sumsq, 1);
    float* rowsq = reinterpret_cast<float*>(smem);
    if (half == 0) rowsq[arow] = sumsq;
    __syncthreads();

    // ---- epilogue: scale by invh * invw, store ----
    float2 iw[4];
#pragma unroll
    for (int nf = 0; nf < 4; nf++) {
        const int col = nw * 32 + nf * 8 + (lane & 3) * 2;
        iw[nf] = *reinterpret_cast<const float2*>(g_inv_w2 + g * 128 + col);
    }
#pragma unroll
    for (int mt = 0; mt < 4; mt++) {
        const int rl = mw * 64 + mt * 16 + (lane >> 2);
        const float ih0 = 1.0f / fmaxf(sqrtf(rowsq[rl]), 1e-12f);
        const float ih1 = 1.0f / fmaxf(sqrtf(rowsq[rl + 8]), 1e-12f);
        const int row = m0 + rl;
#pragma unroll
        for (int nf = 0; nf < 4; nf++) {
            const int col = nw * 32 + nf * 8 + (lane & 3) * 2;
            if (col < K_) {
                float2 v0 = {acc[mt][nf][0] * ih0 * iw[nf].x,
                             acc[mt][nf][1] * ih0 * iw[nf].y};
                float2 v1 = {acc[mt][nf][2] * ih1 * iw[nf].x,
                             acc[mt][nf][3] * ih1 * iw[nf].y};
                *reinterpret_cast<float2*>(out + ((size_t)row * G_ + g) * K_ + col) = v0;
                *reinterpret_cast<float2*>(out + ((size_t)(row + 8) * G_ + g) * K_ + col) = v1;
            }
        }
    }
}

// ---------------------------------------------------------------------------
extern "C" void kernel_launch(void* const* d_in, const int* in_sizes, int n_in,
                              void* d_out, int out_size) {
    const float* h = (const float*)d_in[0];   // [512,100,768]
    const float* w = (const float*)d_in[1];   // [100,768,100]
    float* out = (float*)d_out;               // [512,100,100]
    (void)in_sizes; (void)n_in; (void)out_size;

    const int smem_bytes = 2 * STAGE_BYTES;   // 75776 per CTA -> 2 CTAs/SM
    cudaFuncSetAttribute(gemm_hmma_kernel,
                         cudaFuncAttributeMaxDynamicSharedMemorySize, smem_bytes);

    prep_w_kernel<<<NPREP, 256>>>(w);         // one coalesced pass over w
    combine_w_kernel<<<G_, 128>>>();          // tiny invw table
    dim3 grid(B_ / 128, G_);
    gemm_hmma_kernel<<<grid, 256, smem_bytes>>>(h, out);
}